// round 9
// baseline (speedup 1.0000x reference)
#include <cuda_runtime.h>
#include <math.h>

#define NB 16
#define CELLS 4096
#define SPB 1024
#define NC 513
#define MIC_CELL 2184           // 8*256 + 8*16 + 8
#define PADI(i) ((i) + ((i) >> 4))
#define FULLMASK 0xFFFFFFFFu

// ---------------- scratch --------------------------------------------------
// bin-major excitation spectra: index ((k*NB)+b)*CELLS + c
__device__ __align__(256) float2 g_GE[(size_t)NC * NB * CELLS];   // 269 MB
__device__ float g_micF[NB][2 * NC];
__device__ float2 g_tw[256];       // e^{-2pi i q/512}  (mic radix-2 FFT)
__device__ float2 g_wu[NC];        // e^{-2pi i k/1024} (rfft pack/unpack)
__device__ float2 g_tw512[512];    // e^{-2pi i m/512}

__global__ void init_tw_kernel() {
    int t = threadIdx.x;
    if (t < 256) {
        double a = -2.0 * M_PI * (double)t / 512.0;
        g_tw[t] = make_float2((float)cos(a), (float)sin(a));
    }
    if (t < NC) {
        double a = -2.0 * M_PI * (double)t / 1024.0;
        g_wu[t] = make_float2((float)cos(a), (float)sin(a));
    }
    if (t < 512) {
        double a = -2.0 * M_PI * (double)t / 512.0;
        g_tw512[t] = make_float2((float)cos(a), (float)sin(a));
    }
}

// ---------------- complex helpers ------------------------------------------
__device__ __forceinline__ float2 cadd(float2 a, float2 b) { return make_float2(a.x+b.x, a.y+b.y); }
__device__ __forceinline__ float2 csub(float2 a, float2 b) { return make_float2(a.x-b.x, a.y-b.y); }
__device__ __forceinline__ float2 cmul(float2 a, float2 b) {
    return make_float2(a.x*b.x - a.y*b.y, a.x*b.y + a.y*b.x);
}

// ---------------- K1: ALL 65536 excitation rFFTs, transposed output ---------
// 256 threads = 8 warps; one 512-pt warp-shuffle FFT per warp (one cell).
// No tf staging: smem 34.9 KB -> 4 blocks/SM; 64-reg cap via launch_bounds.
__global__ void __launch_bounds__(256, 4) fft_all_kernel(
    const float* __restrict__ imp,
    const float* __restrict__ noise)
{
    __shared__ float2 smE[8][545];         // per-warp spectra, PADI(512)=544

    const int wid = threadIdx.x >> 5;
    const int ln  = threadIdx.x & 31;
    const int b   = blockIdx.y;
    const int c0  = blockIdx.x << 3;
    const int cell = c0 + wid;
    const size_t rowBC = (size_t)b * CELLS + cell;

    // impulse envelope (16 values) held across lanes 0..15
    float impv = (ln < 16) ? __ldg(imp + rowBC * 16 + ln) : 0.0f;

    const float2* nrow = (const float2*)(noise + rowBC * SPB);

    float2 v[16];
    // ---- load + envelope + pack: v[j] = env(2n)+i*env(2n+1), n = j*32+ln ----
#pragma unroll
    for (int j = 0; j < 16; j++) {
        int n = j * 32 + ln;
        float2 nn = __ldcs(nrow + n);
        float s_m1 = __shfl_sync(FULLMASK, impv, (j > 0) ? (j - 1) : 0);
        float s_0  = __shfl_sync(FULLMASK, impv, j);
        float s_p1 = __shfl_sync(FULLMASK, impv, (j < 15) ? (j + 1) : 15);
        float c0r = ((float)(2 * n) + 0.5f) * 0.015625f - 0.5f;   // in (j-0.5, j+0.5)
        float cc0 = fmaxf(c0r, 0.0f);
        float cc1 = fmaxf(c0r + 0.015625f, 0.0f);
        float fj = (float)j;
        float e0 = (cc0 < fj) ? (s_m1 + (cc0 - (fj - 1.0f)) * (s_0 - s_m1))
                              : (s_0  + (cc0 - fj) * (s_p1 - s_0));
        float e1 = (cc1 < fj) ? (s_m1 + (cc1 - (fj - 1.0f)) * (s_0 - s_m1))
                              : (s_0  + (cc1 - fj) * (s_p1 - s_0));
        e0 = fminf(fmaxf(e0, 0.0f), 1.0f);
        e1 = fminf(fmaxf(e1, 0.0f), 1.0f);
        v[j] = make_float2(e0 * nn.x, e1 * nn.y);
    }

    // ---- in-register DIF-16 (output bit-reversed in slots) -----------------
    {
        const float c8 = 0.92387953251128674f;
        const float s8 = 0.38268343236508977f;
        const float r2 = 0.70710678118654752f;
        const float2 W16[8] = {
            { 1.f, 0.f}, { c8,-s8}, { r2,-r2}, { s8,-c8},
            { 0.f,-1.f}, {-s8,-c8}, {-r2,-r2}, {-c8,-s8} };
        const float2 W8[4] = { {1.f,0.f}, {r2,-r2}, {0.f,-1.f}, {-r2,-r2} };
        const float2 W4[2] = { {1.f,0.f}, {0.f,-1.f} };
#pragma unroll
        for (int i = 0; i < 8; i++) {
            float2 a = v[i], bb = v[i + 8];
            v[i] = cadd(a, bb);
            v[i + 8] = cmul(csub(a, bb), W16[i]);
        }
#pragma unroll
        for (int g = 0; g < 2; g++)
#pragma unroll
            for (int i = 0; i < 4; i++) {
                int p = g * 8 + i;
                float2 a = v[p], bb = v[p + 4];
                v[p] = cadd(a, bb);
                v[p + 4] = cmul(csub(a, bb), W8[i]);
            }
#pragma unroll
        for (int g = 0; g < 4; g++)
#pragma unroll
            for (int i = 0; i < 2; i++) {
                int p = g * 4 + i;
                float2 a = v[p], bb = v[p + 2];
                v[p] = cadd(a, bb);
                v[p + 2] = cmul(csub(a, bb), W4[i]);
            }
#pragma unroll
        for (int g = 0; g < 8; g++) {
            int p = g * 2;
            float2 a = v[p], bb = v[p + 1];
            v[p] = cadd(a, bb);
            v[p + 1] = csub(a, bb);
        }
    }

    // ---- twiddle by W_512^{ln * k1}; slot p holds k1 = bitrev4(p) ----------
    const int BR4[16] = {0,8,4,12,2,10,6,14,1,9,5,13,3,11,7,15};
#pragma unroll
    for (int p = 1; p < 16; p++) {
        float2 w = __ldg((const float2*)g_tw512 + ((ln * BR4[p]) & 511));
        v[p] = cmul(v[p], w);
    }

    // ---- cross-lane DIF-32 (5 shfl stages) ---------------------------------
#pragma unroll
    for (int s = 0; s < 5; s++) {
        int d = 16 >> s;
        float2 w = __ldg((const float2*)g_tw512 + (ln & (d - 1)) * (256 / d));
        bool up = (ln & d) != 0;
#pragma unroll
        for (int p = 0; p < 16; p++) {
            float rx = __shfl_xor_sync(FULLMASK, v[p].x, d);
            float ry = __shfl_xor_sync(FULLMASK, v[p].y, d);
            float2 sum = make_float2(v[p].x + rx, v[p].y + ry);
            float2 dif = cmul(make_float2(rx - v[p].x, ry - v[p].y), w);
            v[p] = up ? dif : sum;
        }
    }

    // ---- transpose to natural order: Z[k2*16+k1], k2 = bitrev5(ln) ---------
    int k2r = (int)(__brev((unsigned)ln) >> 27);
    float2* W = smE[wid];
#pragma unroll
    for (int p = 0; p < 16; p++) {
        W[PADI(k2r * 16 + BR4[p])] = v[p];
    }
    __syncwarp();

    // ---- rfft unpack IN PLACE (each (k, 512-k) pair is thread-private) -----
#pragma unroll
    for (int j = 0; j <= 8; j++) {
        int k = ln + 32 * j;
        if (k <= 256) {
            int kk = 512 - k;
            float2 Zk = W[PADI(k)];
            float2 Zm = W[PADI(kk & 511)];
            // bin k
            {
                float Ax = 0.5f * (Zk.x + Zm.x);
                float Ay = 0.5f * (Zk.y - Zm.y);
                float Bx = 0.5f * (Zk.x - Zm.x);
                float By = 0.5f * (Zk.y + Zm.y);
                float2 Wu = __ldg((const float2*)g_wu + k);
                float wbx = Wu.x * Bx - Wu.y * By;
                float wby = Wu.x * By + Wu.y * Bx;
                W[PADI(k)] = make_float2(Ax + wby, Ay - wbx);
            }
            // bin 512-k  (roles of Zk/Zm swapped)
            if (kk != k) {
                float Ax = 0.5f * (Zm.x + Zk.x);
                float Ay = 0.5f * (Zm.y - Zk.y);
                float Bx = 0.5f * (Zm.x - Zk.x);
                float By = 0.5f * (Zm.y + Zk.y);
                float2 Wu = __ldg((const float2*)g_wu + kk);
                float wbx = Wu.x * Bx - Wu.y * By;
                float wby = Wu.x * By + Wu.y * Bx;
                W[PADI(kk)] = make_float2(Ax + wby, Ay - wbx);   // PADI(512)=544 ok
            }
        }
    }
    __syncthreads();

    // ---- coalesced bin-major write: 8 cells x 8B = 64B rows per k ----------
#pragma unroll
    for (int kb = 0; kb < NC; kb += 32) {
        int k  = kb + (threadIdx.x >> 3);
        int cl = threadIdx.x & 7;
        if (k < NC) {
            float2 E = smE[cl][PADI(k)];
            g_GE[((size_t)k * NB + b) * CELLS + c0 + cl] = E;
        }
    }
}

// ---------------- K2: 16-step scan; block = one bin, state in smem ----------
// tf read directly (2052B-stride scattered; bins k..k+7 share sectors -> L2)
#define SPF 4352
#define SPX 272
#define SPY 17
__global__ void __launch_bounds__(256, 4) scan_kernel(const float* __restrict__ tf) {
    __shared__ float T[2 * SPF];   // 34.8 KB: re/im fields, [f][x][y][z] padded
    const int tid = threadIdx.x;
    const int k   = blockIdx.x;

    for (int i = tid; i < 2 * SPF; i += 256) T[i] = 0.0f;
    __syncthreads();

    for (int b = 0; b < NB; b++) {
        const float2* GE = g_GE + ((size_t)k * NB + b) * CELLS;
        const float*  tb = tf + ((size_t)b * CELLS) * NC + k;

        // V = r*(S + E); tap mic pre-box
#pragma unroll
        for (int it = 0; it < 16; it++) {
            int c = tid + (it << 8);
            float2 E = __ldcs(GE + c);
            float  r = fminf(fmaxf(__ldg(tb + (size_t)c * NC), 0.0f), 1.0f);
            int sa = (c >> 8) * SPX + ((c >> 4) & 15) * SPY + (c & 15);
            float v0 = r * (T[sa]       + E.x);
            float v1 = r * (T[sa + SPF] + E.y);
            T[sa] = v0; T[sa + SPF] = v1;
            if (c == MIC_CELL) {
                g_micF[b][2 * k]     = v0;
                g_micF[b][2 * k + 1] = v1;
            }
        }
        __syncthreads();

        // X pass (stride SPX)
#pragma unroll
        for (int it = 0; it < 2; it++) {
            int l = tid + (it << 8);
            int f = l >> 8, yz = l & 255;
            int off = f * SPF + (yz >> 4) * SPY + (yz & 15);
            float v[16];
#pragma unroll
            for (int x = 0; x < 16; x++) v[x] = T[off + x * SPX];
#pragma unroll
            for (int x = 0; x < 16; x++) {
                float s = v[x];
                if (x > 0)  s += v[x - 1];
                if (x < 15) s += v[x + 1];
                T[off + x * SPX] = s;
            }
        }
        __syncthreads();

        // Y pass (stride SPY)
#pragma unroll
        for (int it = 0; it < 2; it++) {
            int l = tid + (it << 8);
            int f = l >> 8, xz = l & 255;
            int off = f * SPF + (xz >> 4) * SPX + (xz & 15);
            float v[16];
#pragma unroll
            for (int y = 0; y < 16; y++) v[y] = T[off + y * SPY];
#pragma unroll
            for (int y = 0; y < 16; y++) {
                float s = v[y];
                if (y > 0)  s += v[y - 1];
                if (y < 15) s += v[y + 1];
                T[off + y * SPY] = s;
            }
        }
        __syncthreads();

        // Z pass (stride 1)
#pragma unroll
        for (int it = 0; it < 2; it++) {
            int l = tid + (it << 8);
            int f = l >> 8, xy = l & 255;
            int off = f * SPF + (xy >> 4) * SPX + (xy & 15) * SPY;
            float v[16];
#pragma unroll
            for (int z = 0; z < 16; z++) v[z] = T[off + z];
#pragma unroll
            for (int z = 0; z < 16; z++) {
                float s = v[z];
                if (z > 0)  s += v[z - 1];
                if (z < 15) s += v[z + 1];
                T[off + z] = s;
            }
        }
        __syncthreads();
    }
}

// ---------------- radix-2 FFT for the 16 tiny mic inverse transforms --------
__device__ __forceinline__ float2* fft512_r2(float2* a, float2* b, int tid) {
    __syncthreads();
    float2* src = a;
    float2* dst = b;
#pragma unroll
    for (int s = 0; s < 9; s++) {
        int m  = 1 << s;
        int jm = tid & ~(m - 1);
        float2 x0 = src[tid];
        float2 x1 = src[tid + 256];
        float2 w  = g_tw[jm];
        float sx = x0.x + x1.x, sy = x0.y + x1.y;
        float dx = x0.x - x1.x, dy = x0.y - x1.y;
        dst[tid + jm]     = make_float2(sx, sy);
        dst[tid + jm + m] = make_float2(w.x*dx - w.y*dy, w.x*dy + w.y*dx);
        __syncthreads();
        float2* t = src; src = dst; dst = t;
    }
    return src;
}

__global__ void __launch_bounds__(256) mic_kernel(float* __restrict__ out) {
    __shared__ float2 bufA[512];
    __shared__ float2 bufB[512];
    int b   = blockIdx.x;
    int tid = threadIdx.x;
    const float* M = g_micF[b];

    for (int k = tid; k < 512; k += 256) {
        float2 Xk = make_float2(M[2 * k], M[2 * k + 1]);
        int mk = 512 - k;
        float2 Xm = make_float2(M[2 * mk], M[2 * mk + 1]);
        float Ax = 0.5f * (Xk.x + Xm.x);
        float Ay = 0.5f * (Xk.y - Xm.y);
        float Dx = 0.5f * (Xk.x - Xm.x);
        float Dy = 0.5f * (Xk.y + Xm.y);
        float2 W = g_wu[k];
        float cx = W.x * Dx + W.y * Dy;
        float cy = W.x * Dy - W.y * Dx;
        bufA[k] = make_float2(Ax - cy, -(Ay + cx));
    }

    float2* Zr = fft512_r2(bufA, bufB, tid);

    const float s = 1.0f / 512.0f;
    for (int n = tid; n < 512; n += 256) {
        float2 z = Zr[n];
        out[b * 1024 + 2 * n]     =  z.x * s;
        out[b * 1024 + 2 * n + 1] = -z.y * s;
    }
}

// ---------------- launch ----------------------------------------------------
extern "C" void kernel_launch(void* const* d_in, const int* in_sizes, int n_in,
                              void* d_out, int out_size) {
    const float* tf = nullptr;
    const float* imp = nullptr;
    const float* noise = nullptr;
    for (int i = 0; i < n_in; i++) {
        if      (in_sizes[i] == 33619968) tf    = (const float*)d_in[i];
        else if (in_sizes[i] == 1048576)  imp   = (const float*)d_in[i];
        else if (in_sizes[i] == 67108864) noise = (const float*)d_in[i];
    }

    init_tw_kernel<<<1, 544>>>();

    dim3 gf(CELLS / 8, NB);
    fft_all_kernel<<<gf, 256>>>(imp, noise);

    scan_kernel<<<NC, 256>>>(tf);

    mic_kernel<<<NB, 256>>>((float*)d_out);
}

// round 10
// speedup vs baseline: 1.3750x; 1.3750x over previous
#include <cuda_runtime.h>
#include <math.h>

#define NB 16
#define CELLS 4096
#define SPB 1024
#define NC 513
#define MIC_CELL 2184           // 8*256 + 8*16 + 8
#define PADI(i) ((i) + ((i) >> 4))
#define FULLMASK 0xFFFFFFFFu

// ---------------- scratch --------------------------------------------------
// bin-major excitation spectra + clipped tf: index ((k*NB)+b)*CELLS + c
__device__ __align__(256) float2 g_GE[(size_t)NC * NB * CELLS];   // 269 MB
__device__ __align__(256) float  g_Gr[(size_t)NC * NB * CELLS];   // 134 MB
__device__ float g_micF[NB][2 * NC];
__device__ float2 g_tw[256];       // e^{-2pi i q/512}  (mic radix-2 FFT)
__device__ float2 g_wu[NC];        // e^{-2pi i k/1024} (rfft pack/unpack)
__device__ float2 g_tw512[512];    // e^{-2pi i m/512}

__global__ void init_tw_kernel() {
    int t = threadIdx.x;
    if (t < 256) {
        double a = -2.0 * M_PI * (double)t / 512.0;
        g_tw[t] = make_float2((float)cos(a), (float)sin(a));
    }
    if (t < NC) {
        double a = -2.0 * M_PI * (double)t / 1024.0;
        g_wu[t] = make_float2((float)cos(a), (float)sin(a));
    }
    if (t < 512) {
        double a = -2.0 * M_PI * (double)t / 512.0;
        g_tw512[t] = make_float2((float)cos(a), (float)sin(a));
    }
}

// ---------------- complex helpers ------------------------------------------
__device__ __forceinline__ float2 cadd(float2 a, float2 b) { return make_float2(a.x+b.x, a.y+b.y); }
__device__ __forceinline__ float2 csub(float2 a, float2 b) { return make_float2(a.x-b.x, a.y-b.y); }
__device__ __forceinline__ float2 cmul(float2 a, float2 b) {
    return make_float2(a.x*b.x - a.y*b.y, a.x*b.y + a.y*b.x);
}

// ---------------- K1: ALL 65536 excitation rFFTs + Gr, transposed output ----
// 256 threads = 8 warps; one 512-pt warp-shuffle FFT per warp (one cell).
// Lean smem (34.9 KB) -> 4 blocks/SM; tf handled in epilogue via direct __ldg.
__global__ void __launch_bounds__(256, 4) fft_all_kernel(
    const float* __restrict__ tf,
    const float* __restrict__ imp,
    const float* __restrict__ noise)
{
    __shared__ float2 smE[8][545];         // per-warp spectra, PADI(512)=544

    const int wid = threadIdx.x >> 5;
    const int ln  = threadIdx.x & 31;
    const int b   = blockIdx.y;
    const int c0  = blockIdx.x << 3;
    const int cell = c0 + wid;
    const size_t rowBC = (size_t)b * CELLS + cell;

    // impulse envelope (16 values) held across lanes 0..15
    float impv = (ln < 16) ? __ldg(imp + rowBC * 16 + ln) : 0.0f;

    const float2* nrow = (const float2*)(noise + rowBC * SPB);

    float2 v[16];
    // ---- load + envelope + pack: v[j] = env(2n)+i*env(2n+1), n = j*32+ln ----
#pragma unroll
    for (int j = 0; j < 16; j++) {
        int n = j * 32 + ln;
        float2 nn = __ldcs(nrow + n);
        float s_m1 = __shfl_sync(FULLMASK, impv, (j > 0) ? (j - 1) : 0);
        float s_0  = __shfl_sync(FULLMASK, impv, j);
        float s_p1 = __shfl_sync(FULLMASK, impv, (j < 15) ? (j + 1) : 15);
        float c0r = ((float)(2 * n) + 0.5f) * 0.015625f - 0.5f;   // in (j-0.5, j+0.5)
        float cc0 = fmaxf(c0r, 0.0f);
        float cc1 = fmaxf(c0r + 0.015625f, 0.0f);
        float fj = (float)j;
        float e0 = (cc0 < fj) ? (s_m1 + (cc0 - (fj - 1.0f)) * (s_0 - s_m1))
                              : (s_0  + (cc0 - fj) * (s_p1 - s_0));
        float e1 = (cc1 < fj) ? (s_m1 + (cc1 - (fj - 1.0f)) * (s_0 - s_m1))
                              : (s_0  + (cc1 - fj) * (s_p1 - s_0));
        e0 = fminf(fmaxf(e0, 0.0f), 1.0f);
        e1 = fminf(fmaxf(e1, 0.0f), 1.0f);
        v[j] = make_float2(e0 * nn.x, e1 * nn.y);
    }

    // ---- in-register DIF-16 (output bit-reversed in slots) -----------------
    {
        const float c8 = 0.92387953251128674f;
        const float s8 = 0.38268343236508977f;
        const float r2 = 0.70710678118654752f;
        const float2 W16[8] = {
            { 1.f, 0.f}, { c8,-s8}, { r2,-r2}, { s8,-c8},
            { 0.f,-1.f}, {-s8,-c8}, {-r2,-r2}, {-c8,-s8} };
        const float2 W8[4] = { {1.f,0.f}, {r2,-r2}, {0.f,-1.f}, {-r2,-r2} };
        const float2 W4[2] = { {1.f,0.f}, {0.f,-1.f} };
#pragma unroll
        for (int i = 0; i < 8; i++) {
            float2 a = v[i], bb = v[i + 8];
            v[i] = cadd(a, bb);
            v[i + 8] = cmul(csub(a, bb), W16[i]);
        }
#pragma unroll
        for (int g = 0; g < 2; g++)
#pragma unroll
            for (int i = 0; i < 4; i++) {
                int p = g * 8 + i;
                float2 a = v[p], bb = v[p + 4];
                v[p] = cadd(a, bb);
                v[p + 4] = cmul(csub(a, bb), W8[i]);
            }
#pragma unroll
        for (int g = 0; g < 4; g++)
#pragma unroll
            for (int i = 0; i < 2; i++) {
                int p = g * 4 + i;
                float2 a = v[p], bb = v[p + 2];
                v[p] = cadd(a, bb);
                v[p + 2] = cmul(csub(a, bb), W4[i]);
            }
#pragma unroll
        for (int g = 0; g < 8; g++) {
            int p = g * 2;
            float2 a = v[p], bb = v[p + 1];
            v[p] = cadd(a, bb);
            v[p + 1] = csub(a, bb);
        }
    }

    // ---- twiddle by W_512^{ln * k1}; slot p holds k1 = bitrev4(p) ----------
    const int BR4[16] = {0,8,4,12,2,10,6,14,1,9,5,13,3,11,7,15};
#pragma unroll
    for (int p = 1; p < 16; p++) {
        float2 w = __ldg((const float2*)g_tw512 + ((ln * BR4[p]) & 511));
        v[p] = cmul(v[p], w);
    }

    // ---- cross-lane DIF-32 (5 shfl stages) ---------------------------------
#pragma unroll
    for (int s = 0; s < 5; s++) {
        int d = 16 >> s;
        float2 w = __ldg((const float2*)g_tw512 + (ln & (d - 1)) * (256 / d));
        bool up = (ln & d) != 0;
#pragma unroll
        for (int p = 0; p < 16; p++) {
            float rx = __shfl_xor_sync(FULLMASK, v[p].x, d);
            float ry = __shfl_xor_sync(FULLMASK, v[p].y, d);
            float2 sum = make_float2(v[p].x + rx, v[p].y + ry);
            float2 dif = cmul(make_float2(rx - v[p].x, ry - v[p].y), w);
            v[p] = up ? dif : sum;
        }
    }

    // ---- transpose to natural order: Z[k2*16+k1], k2 = bitrev5(ln) ---------
    int k2r = (int)(__brev((unsigned)ln) >> 27);
    float2* W = smE[wid];
#pragma unroll
    for (int p = 0; p < 16; p++) {
        W[PADI(k2r * 16 + BR4[p])] = v[p];
    }
    __syncwarp();

    // ---- rfft unpack IN PLACE (each (k, 512-k) pair is thread-private) -----
#pragma unroll
    for (int j = 0; j <= 8; j++) {
        int k = ln + 32 * j;
        if (k <= 256) {
            int kk = 512 - k;
            float2 Zk = W[PADI(k)];
            float2 Zm = W[PADI(kk & 511)];
            // bin k
            {
                float Ax = 0.5f * (Zk.x + Zm.x);
                float Ay = 0.5f * (Zk.y - Zm.y);
                float Bx = 0.5f * (Zk.x - Zm.x);
                float By = 0.5f * (Zk.y + Zm.y);
                float2 Wu = __ldg((const float2*)g_wu + k);
                float wbx = Wu.x * Bx - Wu.y * By;
                float wby = Wu.x * By + Wu.y * Bx;
                W[PADI(k)] = make_float2(Ax + wby, Ay - wbx);
            }
            // bin 512-k  (roles of Zk/Zm swapped)
            if (kk != k) {
                float Ax = 0.5f * (Zm.x + Zk.x);
                float Ay = 0.5f * (Zm.y - Zk.y);
                float Bx = 0.5f * (Zm.x - Zk.x);
                float By = 0.5f * (Zm.y + Zk.y);
                float2 Wu = __ldg((const float2*)g_wu + kk);
                float wbx = Wu.x * Bx - Wu.y * By;
                float wby = Wu.x * By + Wu.y * Bx;
                W[PADI(kk)] = make_float2(Ax + wby, Ay - wbx);   // PADI(512)=544 ok
            }
        }
    }
    __syncthreads();

    // ---- coalesced bin-major writes: E from smem; Gr straight from tf ------
    {
        const int k_th  = threadIdx.x >> 3;   // 0..31
        const int cl    = threadIdx.x & 7;
        const float* trow = tf + ((size_t)b * CELLS + c0 + cl) * NC;
#pragma unroll
        for (int kb = 0; kb < NC; kb += 32) {
            int k = kb + k_th;
            if (k < NC) {
                size_t o = ((size_t)k * NB + b) * CELLS + c0 + cl;
                g_GE[o] = smE[cl][PADI(k)];
                float r = __ldg(trow + k);   // 2x sector amp; L2 dedups across warps
                g_Gr[o] = fminf(fmaxf(r, 0.0f), 1.0f);
            }
        }
    }
}

// ---------------- K2: 16-step scan; block = one bin, state in smem ----------
#define SPF 4352
#define SPX 272
#define SPY 17
__global__ void __launch_bounds__(256, 4) scan_kernel() {
    __shared__ float T[2 * SPF];   // 34.8 KB: re/im fields, [f][x][y][z] padded
    const int tid = threadIdx.x;
    const int k   = blockIdx.x;

    for (int i = tid; i < 2 * SPF; i += 256) T[i] = 0.0f;
    __syncthreads();

    for (int b = 0; b < NB; b++) {
        const float2* GE = g_GE + ((size_t)k * NB + b) * CELLS;
        const float*  Gr = g_Gr + ((size_t)k * NB + b) * CELLS;

        // V = r*(S + E); tap mic pre-box
#pragma unroll
        for (int it = 0; it < 16; it++) {
            int c = tid + (it << 8);
            float2 E = __ldcs(GE + c);
            float  r = __ldcs(Gr + c);
            int sa = (c >> 8) * SPX + ((c >> 4) & 15) * SPY + (c & 15);
            float v0 = r * (T[sa]       + E.x);
            float v1 = r * (T[sa + SPF] + E.y);
            T[sa] = v0; T[sa + SPF] = v1;
            if (c == MIC_CELL) {
                g_micF[b][2 * k]     = v0;
                g_micF[b][2 * k + 1] = v1;
            }
        }
        __syncthreads();

        // X pass (stride SPX)
#pragma unroll
        for (int it = 0; it < 2; it++) {
            int l = tid + (it << 8);
            int f = l >> 8, yz = l & 255;
            int off = f * SPF + (yz >> 4) * SPY + (yz & 15);
            float v[16];
#pragma unroll
            for (int x = 0; x < 16; x++) v[x] = T[off + x * SPX];
#pragma unroll
            for (int x = 0; x < 16; x++) {
                float s = v[x];
                if (x > 0)  s += v[x - 1];
                if (x < 15) s += v[x + 1];
                T[off + x * SPX] = s;
            }
        }
        __syncthreads();

        // Y pass (stride SPY)
#pragma unroll
        for (int it = 0; it < 2; it++) {
            int l = tid + (it << 8);
            int f = l >> 8, xz = l & 255;
            int off = f * SPF + (xz >> 4) * SPX + (xz & 15);
            float v[16];
#pragma unroll
            for (int y = 0; y < 16; y++) v[y] = T[off + y * SPY];
#pragma unroll
            for (int y = 0; y < 16; y++) {
                float s = v[y];
                if (y > 0)  s += v[y - 1];
                if (y < 15) s += v[y + 1];
                T[off + y * SPY] = s;
            }
        }
        __syncthreads();

        // Z pass (stride 1)
#pragma unroll
        for (int it = 0; it < 2; it++) {
            int l = tid + (it << 8);
            int f = l >> 8, xy = l & 255;
            int off = f * SPF + (xy >> 4) * SPX + (xy & 15) * SPY;
            float v[16];
#pragma unroll
            for (int z = 0; z < 16; z++) v[z] = T[off + z];
#pragma unroll
            for (int z = 0; z < 16; z++) {
                float s = v[z];
                if (z > 0)  s += v[z - 1];
                if (z < 15) s += v[z + 1];
                T[off + z] = s;
            }
        }
        __syncthreads();
    }
}

// ---------------- radix-2 FFT for the 16 tiny mic inverse transforms --------
__device__ __forceinline__ float2* fft512_r2(float2* a, float2* b, int tid) {
    __syncthreads();
    float2* src = a;
    float2* dst = b;
#pragma unroll
    for (int s = 0; s < 9; s++) {
        int m  = 1 << s;
        int jm = tid & ~(m - 1);
        float2 x0 = src[tid];
        float2 x1 = src[tid + 256];
        float2 w  = g_tw[jm];
        float sx = x0.x + x1.x, sy = x0.y + x1.y;
        float dx = x0.x - x1.x, dy = x0.y - x1.y;
        dst[tid + jm]     = make_float2(sx, sy);
        dst[tid + jm + m] = make_float2(w.x*dx - w.y*dy, w.x*dy + w.y*dx);
        __syncthreads();
        float2* t = src; src = dst; dst = t;
    }
    return src;
}

__global__ void __launch_bounds__(256) mic_kernel(float* __restrict__ out) {
    __shared__ float2 bufA[512];
    __shared__ float2 bufB[512];
    int b   = blockIdx.x;
    int tid = threadIdx.x;
    const float* M = g_micF[b];

    for (int k = tid; k < 512; k += 256) {
        float2 Xk = make_float2(M[2 * k], M[2 * k + 1]);
        int mk = 512 - k;
        float2 Xm = make_float2(M[2 * mk], M[2 * mk + 1]);
        float Ax = 0.5f * (Xk.x + Xm.x);
        float Ay = 0.5f * (Xk.y - Xm.y);
        float Dx = 0.5f * (Xk.x - Xm.x);
        float Dy = 0.5f * (Xk.y + Xm.y);
        float2 W = g_wu[k];
        float cx = W.x * Dx + W.y * Dy;
        float cy = W.x * Dy - W.y * Dx;
        bufA[k] = make_float2(Ax - cy, -(Ay + cx));
    }

    float2* Zr = fft512_r2(bufA, bufB, tid);

    const float s = 1.0f / 512.0f;
    for (int n = tid; n < 512; n += 256) {
        float2 z = Zr[n];
        out[b * 1024 + 2 * n]     =  z.x * s;
        out[b * 1024 + 2 * n + 1] = -z.y * s;
    }
}

// ---------------- launch ----------------------------------------------------
extern "C" void kernel_launch(void* const* d_in, const int* in_sizes, int n_in,
                              void* d_out, int out_size) {
    const float* tf = nullptr;
    const float* imp = nullptr;
    const float* noise = nullptr;
    for (int i = 0; i < n_in; i++) {
        if      (in_sizes[i] == 33619968) tf    = (const float*)d_in[i];
        else if (in_sizes[i] == 1048576)  imp   = (const float*)d_in[i];
        else if (in_sizes[i] == 67108864) noise = (const float*)d_in[i];
    }

    init_tw_kernel<<<1, 544>>>();

    dim3 gf(CELLS / 8, NB);
    fft_all_kernel<<<gf, 256>>>(tf, imp, noise);

    scan_kernel<<<NC, 256>>>();

    mic_kernel<<<NB, 256>>>((float*)d_out);
}